// round 1
// baseline (speedup 1.0000x reference)
#include <cuda_runtime.h>

// Problem constants
#define CB 2
#define CT 2048
#define CD 1024
#define CH 16
#define CHD 64
// M = CB*CT = 4096 rows for the projections

// Scratch (allocation-free rule: __device__ globals). 16 MB each.
__device__ float g_q[CB * CH * CT * CHD];
__device__ float g_k[CB * CH * CT * CHD];
__device__ float g_v[CB * CH * CT * CHD];
__device__ float g_att[CB * CH * CT * CHD];

// ---------------------------------------------------------------------------
// Kernel 1: fused QKV projection + bias + RoPE (for Q,K) + transpose to
// [B,H,T,HD]. 128x128 tile, K-tile 16, 256 threads, 8x8 micro-tile.
// out[m][n] = sum_k x[m][k] * W[n][k] + b[n]
// ---------------------------------------------------------------------------
__global__ __launch_bounds__(256) void qkv_rope_kernel(
    const float* __restrict__ x,
    const float* __restrict__ Wq, const float* __restrict__ bq,
    const float* __restrict__ Wk, const float* __restrict__ bk,
    const float* __restrict__ Wv, const float* __restrict__ bv,
    const float* __restrict__ cosb, const float* __restrict__ sinb)
{
    const int z = blockIdx.z;
    const float* W    = (z == 0) ? Wq : (z == 1) ? Wk : Wv;
    const float* bias = (z == 0) ? bq : (z == 1) ? bk : bv;
    float* outp       = (z == 0) ? g_q : (z == 1) ? g_k : g_v;

    __shared__ __align__(16) float As[16][132];   // [k][m], 132*4B row = 16B-aligned
    __shared__ __align__(16) float Bs[16][132];   // [k][n]

    const int tid = threadIdx.x;
    const int m0 = blockIdx.y * 128;
    const int n0 = blockIdx.x * 128;
    const int lr = tid >> 2;          // 0..63
    const int lk = (tid & 3) * 4;     // 0,4,8,12

    float acc[8][8];
#pragma unroll
    for (int i = 0; i < 8; i++)
#pragma unroll
        for (int j = 0; j < 8; j++) acc[i][j] = 0.f;

    const float* Ap = x + (size_t)(m0 + lr) * CD + lk;
    const float* Bp = W + (size_t)(n0 + lr) * CD + lk;
    const int ty = tid >> 4;   // 0..15 (rows)
    const int tx = tid & 15;   // 0..15 (cols)

    for (int k0 = 0; k0 < CD; k0 += 16) {
        float4 a0 = *(const float4*)(Ap + k0);
        float4 a1 = *(const float4*)(Ap + 64 * CD + k0);
        float4 b0 = *(const float4*)(Bp + k0);
        float4 b1 = *(const float4*)(Bp + 64 * CD + k0);

        As[lk + 0][lr] = a0.x; As[lk + 1][lr] = a0.y;
        As[lk + 2][lr] = a0.z; As[lk + 3][lr] = a0.w;
        As[lk + 0][lr + 64] = a1.x; As[lk + 1][lr + 64] = a1.y;
        As[lk + 2][lr + 64] = a1.z; As[lk + 3][lr + 64] = a1.w;
        Bs[lk + 0][lr] = b0.x; Bs[lk + 1][lr] = b0.y;
        Bs[lk + 2][lr] = b0.z; Bs[lk + 3][lr] = b0.w;
        Bs[lk + 0][lr + 64] = b1.x; Bs[lk + 1][lr + 64] = b1.y;
        Bs[lk + 2][lr + 64] = b1.z; Bs[lk + 3][lr + 64] = b1.w;
        __syncthreads();

#pragma unroll
        for (int kk = 0; kk < 16; kk++) {
            float4 av0 = *(const float4*)&As[kk][ty * 8];
            float4 av1 = *(const float4*)&As[kk][ty * 8 + 4];
            float4 bv0 = *(const float4*)&Bs[kk][tx * 8];
            float4 bv1 = *(const float4*)&Bs[kk][tx * 8 + 4];
            float a[8] = {av0.x, av0.y, av0.z, av0.w, av1.x, av1.y, av1.z, av1.w};
            float b[8] = {bv0.x, bv0.y, bv0.z, bv0.w, bv1.x, bv1.y, bv1.z, bv1.w};
#pragma unroll
            for (int i = 0; i < 8; i++)
#pragma unroll
                for (int j = 0; j < 8; j++) acc[i][j] += a[i] * b[j];
        }
        __syncthreads();
    }

    // Epilogue: bias, RoPE (z<2), transpose-store to [B,H,T,HD]
#pragma unroll
    for (int i = 0; i < 8; i++) {
        const int m = m0 + ty * 8 + i;
        const int bb = m >> 11;           // batch (T=2048)
        const int t  = m & (CT - 1);
#pragma unroll
        for (int j = 0; j < 8; j += 2) {
            const int n = n0 + tx * 8 + j;
            float v0 = acc[i][j]     + bias[n];
            float v1 = acc[i][j + 1] + bias[n + 1];
            const int h  = n >> 6;
            const int hd = n & 63;
            float o0 = v0, o1 = v1;
            if (z < 2) {
                const int p = hd >> 1;
                const float c = cosb[t * (CHD / 2) + p];
                const float s = sinb[t * (CHD / 2) + p];
                o0 = v0 * c - v1 * s;
                o1 = v0 * s + v1 * c;
            }
            const size_t base = ((size_t)(bb * CH + h) * CT + t) * CHD + hd;
            outp[base]     = o0;
            outp[base + 1] = o1;
        }
    }
}

// ---------------------------------------------------------------------------
// Kernel 2: causal flash attention, fp32.
// Grid: (32 qtiles, 32 bh), 256 threads. BLOCK_M = BLOCK_N = 64.
// smem: Qs[64][64], KsT[64][68] (k-major, aliased by P[64][68]), Vs[64][68].
// ---------------------------------------------------------------------------
#define ATT_SMEM_FLOATS (64*64 + 64*68 + 64*68 + 3*64)

__global__ __launch_bounds__(256) void attn_kernel()
{
    extern __shared__ __align__(16) float sm[];
    float* Qs   = sm;                 // [row][k]  stride 64
    float* KsT  = Qs + 64 * 64;       // [k][key]  stride 68  (aliased as P[row][key] stride 68)
    float* Vs   = KsT + 64 * 68;      // [key][d]  stride 68
    float* m_sm = Vs + 64 * 68;
    float* l_sm = m_sm + 64;
    float* sc_sm = l_sm + 64;

    const int tid = threadIdx.x;
    const int bh = blockIdx.y;
    const int qt = (gridDim.x - 1) - blockIdx.x;   // heavy tiles first
    const int q0 = qt * 64;

    // Load Q tile (pre-scaled by 1/sqrt(HD) = 0.125)
    {
        const float4* qv = (const float4*)(g_q + ((size_t)bh * CT + q0) * CHD);
        for (int e = tid; e < 1024; e += 256) {
            float4 t4 = qv[e];
            t4.x *= 0.125f; t4.y *= 0.125f; t4.z *= 0.125f; t4.w *= 0.125f;
            *(float4*)&Qs[e * 4] = t4;
        }
    }
    if (tid < 64) { m_sm[tid] = -3.0e38f; l_sm[tid] = 0.f; }

    const int rg = (tid >> 4) * 4;   // row group base (0..60)
    const int cg = (tid & 15) * 4;   // key group (scores) / dim group (PV)

    float acc[4][4];
#pragma unroll
    for (int r = 0; r < 4; r++)
#pragma unroll
        for (int c = 0; c < 4; c++) acc[r][c] = 0.f;

    const int ntile = qt + 1;
    for (int kt = 0; kt < ntile; ++kt) {
        const int k0 = kt * 64;
        __syncthreads();   // protect P (alias of KsT) and Vs from previous iter

        // Load K (transposed to k-major) and V
        {
            const float4* kv4 = (const float4*)(g_k + ((size_t)bh * CT + k0) * CHD);
            const float4* vv4 = (const float4*)(g_v + ((size_t)bh * CT + k0) * CHD);
            for (int e = tid; e < 1024; e += 256) {
                float4 kk4 = kv4[e];
                float4 vv  = vv4[e];
                const int r = e >> 4;         // key index
                const int c = (e & 15) * 4;   // dim index
                KsT[(c + 0) * 68 + r] = kk4.x;
                KsT[(c + 1) * 68 + r] = kk4.y;
                KsT[(c + 2) * 68 + r] = kk4.z;
                KsT[(c + 3) * 68 + r] = kk4.w;
                *(float4*)&Vs[r * 68 + c] = vv;
            }
        }
        __syncthreads();

        // Scores: s[r][c] = sum_k Qs[rg+r][k] * K[cg+c][k]
        float s[4][4];
#pragma unroll
        for (int r = 0; r < 4; r++)
#pragma unroll
            for (int c = 0; c < 4; c++) s[r][c] = 0.f;

#pragma unroll
        for (int k = 0; k < 64; k++) {
            const float4 kb = *(const float4*)&KsT[k * 68 + cg];
            const float kbv[4] = {kb.x, kb.y, kb.z, kb.w};
#pragma unroll
            for (int r = 0; r < 4; r++) {
                const float qa = Qs[(rg + r) * 64 + k];
#pragma unroll
                for (int c = 0; c < 4; c++) s[r][c] += qa * kbv[c];
            }
        }

        if (kt == qt) {   // diagonal tile: mask keys > query
#pragma unroll
            for (int r = 0; r < 4; r++)
#pragma unroll
                for (int c = 0; c < 4; c++)
                    if (cg + c > rg + r) s[r][c] = -3.0e38f;
        }
        __syncthreads();   // scores done: KsT is now free to hold P

        // Online softmax (16 lanes per row-group are contiguous within a warp)
#pragma unroll
        for (int r = 0; r < 4; r++) {
            const int row = rg + r;
            const float m_old = m_sm[row];
            const float l_old = l_sm[row];
            float mx = fmaxf(fmaxf(s[r][0], s[r][1]), fmaxf(s[r][2], s[r][3]));
            mx = fmaxf(mx, __shfl_xor_sync(0xffffffffu, mx, 1));
            mx = fmaxf(mx, __shfl_xor_sync(0xffffffffu, mx, 2));
            mx = fmaxf(mx, __shfl_xor_sync(0xffffffffu, mx, 4));
            mx = fmaxf(mx, __shfl_xor_sync(0xffffffffu, mx, 8));
            const float m_new = fmaxf(m_old, mx);
            float ps = 0.f;
#pragma unroll
            for (int c = 0; c < 4; c++) {
                const float p = __expf(s[r][c] - m_new);
                KsT[row * 68 + cg + c] = p;    // P[row][key]
                ps += p;
            }
            ps += __shfl_xor_sync(0xffffffffu, ps, 1);
            ps += __shfl_xor_sync(0xffffffffu, ps, 2);
            ps += __shfl_xor_sync(0xffffffffu, ps, 4);
            ps += __shfl_xor_sync(0xffffffffu, ps, 8);
            if ((tid & 15) == 0) {
                const float scl = __expf(m_old - m_new);
                m_sm[row] = m_new;
                l_sm[row] = l_old * scl + ps;
                sc_sm[row] = scl;
            }
        }
        __syncthreads();

        // Rescale + PV: acc[r][c] += sum_j P[rg+r][j] * V[j][cg+c]
#pragma unroll
        for (int r = 0; r < 4; r++) {
            const float scl = sc_sm[rg + r];
#pragma unroll
            for (int c = 0; c < 4; c++) acc[r][c] *= scl;
        }
#pragma unroll
        for (int j = 0; j < 64; j++) {
            const float4 vb = *(const float4*)&Vs[j * 68 + cg];
            const float vbv[4] = {vb.x, vb.y, vb.z, vb.w};
#pragma unroll
            for (int r = 0; r < 4; r++) {
                const float pa = KsT[(rg + r) * 68 + j];
#pragma unroll
                for (int c = 0; c < 4; c++) acc[r][c] += pa * vbv[c];
            }
        }
    }

    // Normalize + write [B,H,T,HD]
#pragma unroll
    for (int r = 0; r < 4; r++) {
        const int row = rg + r;
        const float inv = 1.0f / l_sm[row];
        float* op = g_att + ((size_t)bh * CT + q0 + row) * CHD + cg;
#pragma unroll
        for (int c = 0; c < 4; c++) op[c] = acc[r][c] * inv;
    }
}

// ---------------------------------------------------------------------------
// Kernel 3: output projection. A = g_att gathered from [B,H,T,HD] layout.
// out[m][n] = sum_k att[m][k] * Wo[n][k] + bo[n]
// ---------------------------------------------------------------------------
__global__ __launch_bounds__(256) void oproj_kernel(
    const float* __restrict__ Wo, const float* __restrict__ bo,
    float* __restrict__ out)
{
    __shared__ __align__(16) float As[16][132];
    __shared__ __align__(16) float Bs[16][132];

    const int tid = threadIdx.x;
    const int m0 = blockIdx.y * 128;
    const int n0 = blockIdx.x * 128;
    const int lr = tid >> 2;
    const int lk = (tid & 3) * 4;
    const int ty = tid >> 4;
    const int tx = tid & 15;

    const int mA = m0 + lr;          // rows never straddle batch boundary (2048 % 128 == 0)
    const int bbA = mA >> 11, tA = mA & (CT - 1);
    const int mB = mA + 64;
    const int bbB = mB >> 11, tB = mB & (CT - 1);

    const float* Bp = Wo + (size_t)(n0 + lr) * CD + lk;

    float acc[8][8];
#pragma unroll
    for (int i = 0; i < 8; i++)
#pragma unroll
        for (int j = 0; j < 8; j++) acc[i][j] = 0.f;

    for (int k0 = 0; k0 < CD; k0 += 16) {
        const int k = k0 + lk;
        const int h = k >> 6, d = k & 63;
        const float4 a0 = *(const float4*)(g_att + ((size_t)(bbA * CH + h) * CT + tA) * CHD + d);
        const float4 a1 = *(const float4*)(g_att + ((size_t)(bbB * CH + h) * CT + tB) * CHD + d);
        const float4 b0 = *(const float4*)(Bp + k0);
        const float4 b1 = *(const float4*)(Bp + 64 * CD + k0);

        As[lk + 0][lr] = a0.x; As[lk + 1][lr] = a0.y;
        As[lk + 2][lr] = a0.z; As[lk + 3][lr] = a0.w;
        As[lk + 0][lr + 64] = a1.x; As[lk + 1][lr + 64] = a1.y;
        As[lk + 2][lr + 64] = a1.z; As[lk + 3][lr + 64] = a1.w;
        Bs[lk + 0][lr] = b0.x; Bs[lk + 1][lr] = b0.y;
        Bs[lk + 2][lr] = b0.z; Bs[lk + 3][lr] = b0.w;
        Bs[lk + 0][lr + 64] = b1.x; Bs[lk + 1][lr + 64] = b1.y;
        Bs[lk + 2][lr + 64] = b1.z; Bs[lk + 3][lr + 64] = b1.w;
        __syncthreads();

#pragma unroll
        for (int kk = 0; kk < 16; kk++) {
            float4 av0 = *(const float4*)&As[kk][ty * 8];
            float4 av1 = *(const float4*)&As[kk][ty * 8 + 4];
            float4 bv0 = *(const float4*)&Bs[kk][tx * 8];
            float4 bv1 = *(const float4*)&Bs[kk][tx * 8 + 4];
            float a[8] = {av0.x, av0.y, av0.z, av0.w, av1.x, av1.y, av1.z, av1.w};
            float b[8] = {bv0.x, bv0.y, bv0.z, bv0.w, bv1.x, bv1.y, bv1.z, bv1.w};
#pragma unroll
            for (int i = 0; i < 8; i++)
#pragma unroll
                for (int j = 0; j < 8; j++) acc[i][j] += a[i] * b[j];
        }
        __syncthreads();
    }

#pragma unroll
    for (int i = 0; i < 8; i++) {
        const int m = m0 + ty * 8 + i;
#pragma unroll
        for (int j = 0; j < 8; j++) {
            const int n = n0 + tx * 8 + j;
            out[(size_t)m * CD + n] = acc[i][j] + bo[n];
        }
    }
}

// ---------------------------------------------------------------------------
extern "C" void kernel_launch(void* const* d_in, const int* in_sizes, int n_in,
                              void* d_out, int out_size)
{
    const float* x    = (const float*)d_in[0];
    const float* cosb = (const float*)d_in[1];
    const float* sinb = (const float*)d_in[2];
    const float* Wq   = (const float*)d_in[3];
    const float* bq   = (const float*)d_in[4];
    const float* Wk   = (const float*)d_in[5];
    const float* bk   = (const float*)d_in[6];
    const float* Wv   = (const float*)d_in[7];
    const float* bv   = (const float*)d_in[8];
    const float* Wo   = (const float*)d_in[9];
    const float* bo   = (const float*)d_in[10];
    float* out = (float*)d_out;

    const int att_smem = ATT_SMEM_FLOATS * (int)sizeof(float);   // ~52 KB
    cudaFuncSetAttribute(attn_kernel, cudaFuncAttributeMaxDynamicSharedMemorySize, att_smem);

    dim3 g1(CD / 128, (CB * CT) / 128, 3);   // (8, 32, 3)
    qkv_rope_kernel<<<g1, 256>>>(x, Wq, bq, Wk, bk, Wv, bv, cosb, sinb);

    dim3 g2(CT / 64, CB * CH);               // (32, 32)
    attn_kernel<<<g2, 256, att_smem>>>();

    dim3 g3(CD / 128, (CB * CT) / 128);      // (8, 32)
    oproj_kernel<<<g3, 256>>>(Wo, bo, out);
}

// round 6
// speedup vs baseline: 1.4648x; 1.4648x over previous
#include <cuda_runtime.h>
#include <cuda_bf16.h>
#include <cstdint>

// Problem constants
#define CB 2
#define CT 2048
#define CD 1024
#define CH 16
#define CHD 64
#define MROWS (CB * CT)          // 4096

// ---------------------------------------------------------------------------
// Scratch (__device__ globals; allocation-free rule)
// ---------------------------------------------------------------------------
__device__ float g_q[CB * CH * CT * CHD];
__device__ float g_k[CB * CH * CT * CHD];
__device__ float g_v[CB * CH * CT * CHD];
__device__ __nv_bfloat16 g_ah[CB * CH * CT * CHD];   // attention out, hi
__device__ __nv_bfloat16 g_al[CB * CH * CT * CHD];   // attention out, lo
__device__ __nv_bfloat16 g_xh[MROWS * CD], g_xl[MROWS * CD];
__device__ __nv_bfloat16 g_wqh[CD * CD], g_wql[CD * CD];
__device__ __nv_bfloat16 g_wkh[CD * CD], g_wkl[CD * CD];
__device__ __nv_bfloat16 g_wvh[CD * CD], g_wvl[CD * CD];
__device__ __nv_bfloat16 g_woh[CD * CD], g_wol[CD * CD];

// ---------------------------------------------------------------------------
// PTX helpers (plain sm_103-target features only: cp.async / ldmatrix / mma.sync)
// ---------------------------------------------------------------------------
__device__ __forceinline__ uint32_t smem_u32(const void* p) {
    uint32_t a;
    asm("{ .reg .u64 t; cvta.to.shared.u64 t, %1; cvt.u32.u64 %0, t; }" : "=r"(a) : "l"(p));
    return a;
}
#define CP16(dst, gsrc)   asm volatile("cp.async.cg.shared.global [%0], [%1], 16;" :: "r"(dst), "l"(gsrc) : "memory")
#define CP_COMMIT()       asm volatile("cp.async.commit_group;" ::: "memory")
#define CP_WAIT2()        asm volatile("cp.async.wait_group 2;" ::: "memory")

__device__ __forceinline__ void ldsm_x4(uint32_t* r, uint32_t a) {
    asm volatile("ldmatrix.sync.aligned.m8n8.x4.shared.b16 {%0,%1,%2,%3}, [%4];"
                 : "=r"(r[0]), "=r"(r[1]), "=r"(r[2]), "=r"(r[3]) : "r"(a));
}
__device__ __forceinline__ void ldsm_x2(uint32_t* r, uint32_t a) {
    asm volatile("ldmatrix.sync.aligned.m8n8.x2.shared.b16 {%0,%1}, [%2];"
                 : "=r"(r[0]), "=r"(r[1]) : "r"(a));
}
__device__ __forceinline__ void mma_bf16(float* d, const uint32_t* a, const uint32_t* b) {
    asm volatile("mma.sync.aligned.m16n8k16.row.col.f32.bf16.bf16.f32 "
                 "{%0,%1,%2,%3}, {%4,%5,%6,%7}, {%8,%9}, {%0,%1,%2,%3};"
                 : "+f"(d[0]), "+f"(d[1]), "+f"(d[2]), "+f"(d[3])
                 : "r"(a[0]), "r"(a[1]), "r"(a[2]), "r"(a[3]), "r"(b[0]), "r"(b[1]));
}

// ---------------------------------------------------------------------------
// Kernel 0: fp32 -> (bf16 hi, bf16 lo) conversion for x and the 4 weights
// ---------------------------------------------------------------------------
__global__ __launch_bounds__(256) void convert_kernel(
    const float* __restrict__ x,
    const float* __restrict__ Wq, const float* __restrict__ Wk,
    const float* __restrict__ Wv, const float* __restrict__ Wo)
{
    const int z = blockIdx.z;
    const float* src; __nv_bfloat16 *dh, *dl; int n4;
    switch (z) {
        case 0: src = x;  dh = g_xh;  dl = g_xl;  n4 = MROWS * CD / 4; break;
        case 1: src = Wq; dh = g_wqh; dl = g_wql; n4 = CD * CD / 4;    break;
        case 2: src = Wk; dh = g_wkh; dl = g_wkl; n4 = CD * CD / 4;    break;
        case 3: src = Wv; dh = g_wvh; dl = g_wvl; n4 = CD * CD / 4;    break;
        default:src = Wo; dh = g_woh; dl = g_wol; n4 = CD * CD / 4;    break;
    }
    for (int i = blockIdx.x * 256 + threadIdx.x; i < n4; i += gridDim.x * 256) {
        float4 v = ((const float4*)src)[i];
        __nv_bfloat16 h0 = __float2bfloat16(v.x), h1 = __float2bfloat16(v.y);
        __nv_bfloat16 h2 = __float2bfloat16(v.z), h3 = __float2bfloat16(v.w);
        __nv_bfloat162 ph0; ph0.x = h0; ph0.y = h1;
        __nv_bfloat162 ph1; ph1.x = h2; ph1.y = h3;
        __nv_bfloat162 pl0, pl1;
        pl0.x = __float2bfloat16(v.x - __bfloat162float(h0));
        pl0.y = __float2bfloat16(v.y - __bfloat162float(h1));
        pl1.x = __float2bfloat16(v.z - __bfloat162float(h2));
        pl1.y = __float2bfloat16(v.w - __bfloat162float(h3));
        ((__nv_bfloat162*)dh)[2 * i]     = ph0;
        ((__nv_bfloat162*)dh)[2 * i + 1] = ph1;
        ((__nv_bfloat162*)dl)[2 * i]     = pl0;
        ((__nv_bfloat162*)dl)[2 * i + 1] = pl1;
    }
}

// ---------------------------------------------------------------------------
// Kernel 1: HMMA GEMM (mma.sync bf16, fp32-emulated via hi/lo split, 3 passes)
// C[m][n] = sum_k A[m][k] * W[n][k]   (+bias, +RoPE/layout epilogue per mode)
// Tile M=128 (blockIdx.y) x N=128 (blockIdx.x), BK=32, 3-stage cp.async.
// mode = modeBase + blockIdx.z:  0=Q(rope) 1=K(rope) 2=V 3=Oproj
// Stage layout (bf16 elems, row stride 40): Ah[128][40] Al Bh Bl
// ---------------------------------------------------------------------------
#define LDA 40
#define TILE_B (128 * LDA * 2)          // 10240 bytes per sub-tile
#define STAGE_B (4 * TILE_B)            // 40960 bytes per stage
#define GEMM_SMEM (3 * STAGE_B)         // 122880

__global__ __launch_bounds__(256, 1) void gemm_hmma_kernel(
    const float* __restrict__ b0, const float* __restrict__ b1, const float* __restrict__ b2,
    const float* __restrict__ cosb, const float* __restrict__ sinb,
    float* __restrict__ outO, int modeBase)
{
    extern __shared__ __align__(16) char smem[];
    const int mode = modeBase + blockIdx.z;

    const __nv_bfloat16 *Ah_g, *Al_g, *Wh, *Wl; const float* bias;
    if      (mode == 0) { Ah_g = g_xh; Al_g = g_xl; Wh = g_wqh; Wl = g_wql; bias = b0; }
    else if (mode == 1) { Ah_g = g_xh; Al_g = g_xl; Wh = g_wkh; Wl = g_wkl; bias = b1; }
    else if (mode == 2) { Ah_g = g_xh; Al_g = g_xl; Wh = g_wvh; Wl = g_wvl; bias = b2; }
    else                { Ah_g = g_ah; Al_g = g_al; Wh = g_woh; Wl = g_wol; bias = b0; }

    const int tid = threadIdx.x;
    const int lane = tid & 31;
    const int wid = tid >> 5;
    const int wm = wid & 3;          // 4 warps along M (32 rows each)
    const int wn = wid >> 2;         // 2 warps along N (64 cols each)
    const int n0 = blockIdx.x * 128;
    const int m0 = blockIdx.y * 128;
    const uint32_t sb = smem_u32(smem);

    // cp.async fill of K-chunk c (k in [32c, 32c+32)) into stage s
    auto fill = [&](int c, int s) {
        const uint32_t stg = sb + s * STAGE_B;
#pragma unroll
        for (int i = 0; i < 2; i++) {
            const int idx = tid + i * 256;      // 0..511
            const int r = idx >> 2, q = idx & 3;
            const int kk = c * 32 + q * 8;
            size_t aoff;
            if (mode < 3) {
                aoff = (size_t)(m0 + r) * CD + kk;
            } else {
                const int m = m0 + r;
                aoff = (((size_t)((m >> 11) * CH + (kk >> 6))) * CT + (m & (CT - 1))) * CHD + (kk & 63);
            }
            const uint32_t da = stg + (uint32_t)(r * LDA + q * 8) * 2;
            CP16(da,          __cvta_generic_to_global(Ah_g + aoff));
            CP16(da + TILE_B, __cvta_generic_to_global(Al_g + aoff));
            const size_t boff = (size_t)(n0 + r) * CD + kk;
            CP16(da + 2 * TILE_B, __cvta_generic_to_global(Wh + boff));
            CP16(da + 3 * TILE_B, __cvta_generic_to_global(Wl + boff));
        }
    };

    // ldmatrix base offsets (bytes within a stage)
    const uint32_t offA = (uint32_t)((32 * wm + (lane & 15)) * LDA + (lane >> 4) * 8) * 2;
    const uint32_t offB = (uint32_t)((64 * wn + (lane & 7)) * LDA + ((lane >> 3) & 1) * 8) * 2;

    float d[2][8][4];
#pragma unroll
    for (int f = 0; f < 2; f++)
#pragma unroll
        for (int j = 0; j < 8; j++)
#pragma unroll
            for (int e = 0; e < 4; e++) d[f][j][e] = 0.f;

    fill(0, 0); CP_COMMIT();
    fill(1, 1); CP_COMMIT();

    for (int c = 0; c < 32; c++) {
        const int s = c % 3;
        if (c + 2 < 32) fill(c + 2, (c + 2) % 3);
        CP_COMMIT();
        CP_WAIT2();
        __syncthreads();

        const uint32_t stg = sb + s * STAGE_B;
#pragma unroll
        for (int kk = 0; kk < 2; kk++) {
            uint32_t ah[2][4], al[2][4], bh[8][2], bl[8][2];
            const uint32_t ka = stg + offA + kk * 32;        // 16 elems = 32B
            const uint32_t kb = stg + offB + kk * 32;
#pragma unroll
            for (int f = 0; f < 2; f++) {
                ldsm_x4(ah[f], ka + f * (16 * LDA * 2));
                ldsm_x4(al[f], ka + f * (16 * LDA * 2) + TILE_B);
            }
#pragma unroll
            for (int j = 0; j < 8; j++) {
                ldsm_x2(bh[j], kb + j * (8 * LDA * 2) + 2 * TILE_B);
                ldsm_x2(bl[j], kb + j * (8 * LDA * 2) + 3 * TILE_B);
            }
#pragma unroll
            for (int f = 0; f < 2; f++)
#pragma unroll
                for (int j = 0; j < 8; j++) {
                    mma_bf16(d[f][j], ah[f], bh[j]);
                    mma_bf16(d[f][j], ah[f], bl[j]);
                    mma_bf16(d[f][j], al[f], bh[j]);
                }
        }
        __syncthreads();
    }

    // Epilogue. Thread holds (row, row+8) x (n, n+1) per fragment.
    const int q4 = lane >> 2;           // 0..7
    const int p2 = (lane & 3) * 2;      // 0,2,4,6
#pragma unroll
    for (int f = 0; f < 2; f++) {
#pragma unroll
        for (int rr = 0; rr < 2; rr++) {
            const int mrow = m0 + 32 * wm + 16 * f + q4 + rr * 8;
            const int bb = mrow >> 11;
            const int tt = mrow & (CT - 1);
#pragma unroll
            for (int j = 0; j < 8; j++) {
                const int n = n0 + 64 * wn + 8 * j + p2;
                const float2 bv = *(const float2*)(bias + n);
                float v0 = d[f][j][rr * 2 + 0] + bv.x;
                float v1 = d[f][j][rr * 2 + 1] + bv.y;
                if (mode == 3) {
                    *(float2*)(outO + (size_t)mrow * CD + n) = make_float2(v0, v1);
                } else {
                    float* op = (mode == 0 ? g_q : mode == 1 ? g_k : g_v);
                    const size_t base = (((size_t)(bb * CH + (n >> 6))) * CT + tt) * CHD + (n & 63);
                    if (mode < 2) {
                        const int p = (n & 63) >> 1;
                        const float cc = cosb[tt * (CHD / 2) + p];
                        const float ss = sinb[tt * (CHD / 2) + p];
                        *(float2*)(op + base) = make_float2(v0 * cc - v1 * ss, v0 * ss + v1 * cc);
                    } else {
                        *(float2*)(op + base) = make_float2(v0, v1);
                    }
                }
            }
        }
    }
}

// ---------------------------------------------------------------------------
// Kernel 2: causal flash attention, fp32; epilogue emits bf16 hi/lo for oproj.
// ---------------------------------------------------------------------------
#define ATT_SMEM_FLOATS (64*64 + 64*68 + 64*68 + 3*64)

__global__ __launch_bounds__(256) void attn_kernel()
{
    extern __shared__ __align__(16) float sm[];
    float* Qs   = sm;
    float* KsT  = Qs + 64 * 64;       // aliased as P after scores
    float* Vs   = KsT + 64 * 68;
    float* m_sm = Vs + 64 * 68;
    float* l_sm = m_sm + 64;
    float* sc_sm = l_sm + 64;

    const int tid = threadIdx.x;
    const int bh = blockIdx.y;
    const int qt = (gridDim.x - 1) - blockIdx.x;   // heavy tiles first
    const int q0 = qt * 64;

    {
        const float4* qv = (const float4*)(g_q + ((size_t)bh * CT + q0) * CHD);
        for (int e = tid; e < 1024; e += 256) {
            float4 t4 = qv[e];
            t4.x *= 0.125f; t4.y *= 0.125f; t4.z *= 0.125f; t4.w *= 0.125f;
            *(float4*)&Qs[e * 4] = t4;
        }
    }
    if (tid < 64) { m_sm[tid] = -3.0e38f; l_sm[tid] = 0.f; }

    const int rg = (tid >> 4) * 4;
    const int cg = (tid & 15) * 4;

    float acc[4][4];
#pragma unroll
    for (int r = 0; r < 4; r++)
#pragma unroll
        for (int c = 0; c < 4; c++) acc[r][c] = 0.f;

    const int ntile = qt + 1;
    for (int kt = 0; kt < ntile; ++kt) {
        const int k0 = kt * 64;
        __syncthreads();
        {
            const float4* kv4 = (const float4*)(g_k + ((size_t)bh * CT + k0) * CHD);
            const float4* vv4 = (const float4*)(g_v + ((size_t)bh * CT + k0) * CHD);
            for (int e = tid; e < 1024; e += 256) {
                float4 kk4 = kv4[e];
                float4 vv  = vv4[e];
                const int r = e >> 4;
                const int c = (e & 15) * 4;
                KsT[(c + 0) * 68 + r] = kk4.x;
                KsT[(c + 1) * 68 + r] = kk4.y;
                KsT[(c + 2) * 68 + r] = kk4.z;
                KsT[(c + 3) * 68 + r] = kk4.w;
                *(float4*)&Vs[r * 68 + c] = vv;
            }
        }
        __syncthreads();

        float s[4][4];
#pragma unroll
        for (int r = 0; r < 4; r++)
#pragma unroll
            for (int c = 0; c < 4; c++) s[r][c] = 0.f;
#pragma unroll
        for (int k = 0; k < 64; k++) {
            const float4 kb = *(const float4*)&KsT[k * 68 + cg];
            const float kbv[4] = {kb.x, kb.y, kb.z, kb.w};
#pragma unroll
            for (int r = 0; r < 4; r++) {
                const float qa = Qs[(rg + r) * 64 + k];
#pragma unroll
                for (int c = 0; c < 4; c++) s[r][c] += qa * kbv[c];
            }
        }
        if (kt == qt) {
#pragma unroll
            for (int r = 0; r < 4; r++)
#pragma unroll
                for (int c = 0; c < 4; c++)
                    if (cg + c > rg + r) s[r][c] = -3.0e38f;
        }
        __syncthreads();

#pragma unroll
        for (int r = 0; r < 4; r++) {
            const int row = rg + r;
            const float m_old = m_sm[row];
            const float l_old = l_sm[row];
            float mx = fmaxf(fmaxf(s[r][0], s[r][1]), fmaxf(s[r][2], s[r][3]));
            mx = fmaxf(mx, __shfl_xor_sync(0xffffffffu, mx, 1));
            mx = fmaxf(mx, __shfl_xor_sync(0xffffffffu, mx, 2));
            mx = fmaxf(mx, __shfl_xor_sync(0xffffffffu, mx, 4));
            mx = fmaxf(mx, __shfl_xor_sync(0xffffffffu, mx, 8));
            const float m_new = fmaxf(m_old, mx);
            float ps = 0.f;
#pragma unroll
            for (int c = 0; c < 4; c++) {
                const float p = __expf(s[r][c] - m_new);
                KsT[row * 68 + cg + c] = p;
                ps += p;
            }
            ps += __shfl_xor_sync(0xffffffffu, ps, 1);
            ps += __shfl_xor_sync(0xffffffffu, ps, 2);
            ps += __shfl_xor_sync(0xffffffffu, ps, 4);
            ps += __shfl_xor_sync(0xffffffffu, ps, 8);
            if ((tid & 15) == 0) {
                const float scl = __expf(m_old - m_new);
                m_sm[row] = m_new;
                l_sm[row] = l_old * scl + ps;
                sc_sm[row] = scl;
            }
        }
        __syncthreads();

#pragma unroll
        for (int r = 0; r < 4; r++) {
            const float scl = sc_sm[rg + r];
#pragma unroll
            for (int c = 0; c < 4; c++) acc[r][c] *= scl;
        }
#pragma unroll
        for (int j = 0; j < 64; j++) {
            const float4 vb = *(const float4*)&Vs[j * 68 + cg];
            const float vbv[4] = {vb.x, vb.y, vb.z, vb.w};
#pragma unroll
            for (int r = 0; r < 4; r++) {
                const float pa = KsT[(rg + r) * 68 + j];
#pragma unroll
                for (int c = 0; c < 4; c++) acc[r][c] += pa * vbv[c];
            }
        }
    }

    // Normalize + write bf16 hi/lo to [B,H,T,HD]
#pragma unroll
    for (int r = 0; r < 4; r++) {
        const int row = rg + r;
        const float inv = 1.0f / l_sm[row];
        const size_t ob = ((size_t)bh * CT + q0 + row) * CHD + cg;
#pragma unroll
        for (int c = 0; c < 4; c++) {
            const float o = acc[r][c] * inv;
            const __nv_bfloat16 h = __float2bfloat16(o);
            g_ah[ob + c] = h;
            g_al[ob + c] = __float2bfloat16(o - __bfloat162float(h));
        }
    }
}

// ---------------------------------------------------------------------------
extern "C" void kernel_launch(void* const* d_in, const int* in_sizes, int n_in,
                              void* d_out, int out_size)
{
    const float* x    = (const float*)d_in[0];
    const float* cosb = (const float*)d_in[1];
    const float* sinb = (const float*)d_in[2];
    const float* Wq   = (const float*)d_in[3];
    const float* bq   = (const float*)d_in[4];
    const float* Wk   = (const float*)d_in[5];
    const float* bk   = (const float*)d_in[6];
    const float* Wv   = (const float*)d_in[7];
    const float* bv   = (const float*)d_in[8];
    const float* Wo   = (const float*)d_in[9];
    const float* bo   = (const float*)d_in[10];
    float* out = (float*)d_out;

    cudaFuncSetAttribute(gemm_hmma_kernel, cudaFuncAttributeMaxDynamicSharedMemorySize, GEMM_SMEM);
    cudaFuncSetAttribute(attn_kernel, cudaFuncAttributeMaxDynamicSharedMemorySize,
                         ATT_SMEM_FLOATS * (int)sizeof(float));

    // 1) fp32 -> bf16 hi/lo conversions
    convert_kernel<<<dim3(512, 1, 5), 256>>>(x, Wq, Wk, Wv, Wo);

    // 2) QKV projections + bias + RoPE (HMMA)
    gemm_hmma_kernel<<<dim3(CD / 128, MROWS / 128, 3), 256, GEMM_SMEM>>>(
        bq, bk, bv, cosb, sinb, nullptr, 0);

    // 3) causal flash attention (fp32) -> bf16 hi/lo attention output
    attn_kernel<<<dim3(CT / 64, CB * CH), 256, ATT_SMEM_FLOATS * (int)sizeof(float)>>>();

    // 4) output projection (HMMA) -> d_out
    gemm_hmma_kernel<<<dim3(CD / 128, MROWS / 128, 1), 256, GEMM_SMEM>>>(
        bo, bo, bo, cosb, sinb, out, 3);
}

// round 7
// speedup vs baseline: 2.5880x; 1.7667x over previous
#include <cuda_runtime.h>
#include <cuda_bf16.h>
#include <cstdint>

// Problem constants
#define CB 2
#define CT 2048
#define CD 1024
#define CH 16
#define CHD 64
#define MROWS (CB * CT)          // 4096

// ---------------------------------------------------------------------------
// Scratch (__device__ globals; allocation-free rule)
// ---------------------------------------------------------------------------
__device__ __nv_bfloat16 g_qh[CB * CH * CT * CHD], g_ql[CB * CH * CT * CHD]; // Q hi/lo [B,H,T,HD] (pre-scaled 0.125)
__device__ __nv_bfloat16 g_kh[CB * CH * CT * CHD], g_kl[CB * CH * CT * CHD]; // K hi/lo [B,H,T,HD]
__device__ __nv_bfloat16 g_vth[CB * CH * CT * CHD], g_vtl[CB * CH * CT * CHD]; // V hi/lo TRANSPOSED [B,H,HD,T]
__device__ __nv_bfloat16 g_ah[CB * CH * CT * CHD], g_al[CB * CH * CT * CHD]; // attn out hi/lo [B,H,T,HD]
__device__ __nv_bfloat16 g_xh[MROWS * CD], g_xl[MROWS * CD];
__device__ __nv_bfloat16 g_wqh[CD * CD], g_wql[CD * CD];
__device__ __nv_bfloat16 g_wkh[CD * CD], g_wkl[CD * CD];
__device__ __nv_bfloat16 g_wvh[CD * CD], g_wvl[CD * CD];
__device__ __nv_bfloat16 g_woh[CD * CD], g_wol[CD * CD];

// ---------------------------------------------------------------------------
// PTX helpers (plain sm_103-target features only: cp.async / ldmatrix / mma.sync)
// ---------------------------------------------------------------------------
__device__ __forceinline__ uint32_t smem_u32(const void* p) {
    uint32_t a;
    asm("{ .reg .u64 t; cvta.to.shared.u64 t, %1; cvt.u32.u64 %0, t; }" : "=r"(a) : "l"(p));
    return a;
}
#define CP16(dst, gsrc)   asm volatile("cp.async.cg.shared.global [%0], [%1], 16;" :: "r"(dst), "l"(gsrc) : "memory")
#define CP_COMMIT()       asm volatile("cp.async.commit_group;" ::: "memory")
#define CP_WAIT2()        asm volatile("cp.async.wait_group 2;" ::: "memory")
#define CP_WAIT1()        asm volatile("cp.async.wait_group 1;" ::: "memory")
#define CP_WAIT0()        asm volatile("cp.async.wait_group 0;" ::: "memory")

__device__ __forceinline__ void ldsm_x4(uint32_t* r, uint32_t a) {
    asm volatile("ldmatrix.sync.aligned.m8n8.x4.shared.b16 {%0,%1,%2,%3}, [%4];"
                 : "=r"(r[0]), "=r"(r[1]), "=r"(r[2]), "=r"(r[3]) : "r"(a));
}
__device__ __forceinline__ void ldsm_x2(uint32_t* r, uint32_t a) {
    asm volatile("ldmatrix.sync.aligned.m8n8.x2.shared.b16 {%0,%1}, [%2];"
                 : "=r"(r[0]), "=r"(r[1]) : "r"(a));
}
__device__ __forceinline__ void mma_bf16(float* d, const uint32_t* a, const uint32_t* b) {
    asm volatile("mma.sync.aligned.m16n8k16.row.col.f32.bf16.bf16.f32 "
                 "{%0,%1,%2,%3}, {%4,%5,%6,%7}, {%8,%9}, {%0,%1,%2,%3};"
                 : "+f"(d[0]), "+f"(d[1]), "+f"(d[2]), "+f"(d[3])
                 : "r"(a[0]), "r"(a[1]), "r"(a[2]), "r"(a[3]), "r"(b[0]), "r"(b[1]));
}
__device__ __forceinline__ uint32_t packbf2(float a, float b) {
    __nv_bfloat162 t = __floats2bfloat162_rn(a, b);
    return *(uint32_t*)&t;
}

// ---------------------------------------------------------------------------
// Kernel 0: fp32 -> (bf16 hi, bf16 lo) conversion for x and the 4 weights
// ---------------------------------------------------------------------------
__global__ __launch_bounds__(256) void convert_kernel(
    const float* __restrict__ x,
    const float* __restrict__ Wq, const float* __restrict__ Wk,
    const float* __restrict__ Wv, const float* __restrict__ Wo)
{
    const int z = blockIdx.z;
    const float* src; __nv_bfloat16 *dh, *dl; int n4;
    switch (z) {
        case 0: src = x;  dh = g_xh;  dl = g_xl;  n4 = MROWS * CD / 4; break;
        case 1: src = Wq; dh = g_wqh; dl = g_wql; n4 = CD * CD / 4;    break;
        case 2: src = Wk; dh = g_wkh; dl = g_wkl; n4 = CD * CD / 4;    break;
        case 3: src = Wv; dh = g_wvh; dl = g_wvl; n4 = CD * CD / 4;    break;
        default:src = Wo; dh = g_woh; dl = g_wol; n4 = CD * CD / 4;    break;
    }
    for (int i = blockIdx.x * 256 + threadIdx.x; i < n4; i += gridDim.x * 256) {
        float4 v = ((const float4*)src)[i];
        __nv_bfloat16 h0 = __float2bfloat16(v.x), h1 = __float2bfloat16(v.y);
        __nv_bfloat16 h2 = __float2bfloat16(v.z), h3 = __float2bfloat16(v.w);
        __nv_bfloat162 ph0; ph0.x = h0; ph0.y = h1;
        __nv_bfloat162 ph1; ph1.x = h2; ph1.y = h3;
        __nv_bfloat162 pl0, pl1;
        pl0.x = __float2bfloat16(v.x - __bfloat162float(h0));
        pl0.y = __float2bfloat16(v.y - __bfloat162float(h1));
        pl1.x = __float2bfloat16(v.z - __bfloat162float(h2));
        pl1.y = __float2bfloat16(v.w - __bfloat162float(h3));
        ((__nv_bfloat162*)dh)[2 * i]     = ph0;
        ((__nv_bfloat162*)dh)[2 * i + 1] = ph1;
        ((__nv_bfloat162*)dl)[2 * i]     = pl0;
        ((__nv_bfloat162*)dl)[2 * i + 1] = pl1;
    }
}

// ---------------------------------------------------------------------------
// Kernel 1: HMMA GEMM (validated R6). Mainloop unchanged; epilogue now emits
// bf16 hi/lo for Q/K ([B,H,T,HD], Q scaled 0.125) and V (transposed [B,H,HD,T]).
// mode = modeBase + blockIdx.z:  0=Q(rope) 1=K(rope) 2=V 3=Oproj(f32 out)
// ---------------------------------------------------------------------------
#define LDA 40
#define TILE_B (128 * LDA * 2)          // 10240 bytes per sub-tile
#define STAGE_B (4 * TILE_B)            // 40960 bytes per stage
#define GEMM_SMEM (3 * STAGE_B)         // 122880

__global__ __launch_bounds__(256, 1) void gemm_hmma_kernel(
    const float* __restrict__ b0, const float* __restrict__ b1, const float* __restrict__ b2,
    const float* __restrict__ cosb, const float* __restrict__ sinb,
    float* __restrict__ outO, int modeBase)
{
    extern __shared__ __align__(16) char smem[];
    const int mode = modeBase + blockIdx.z;

    const __nv_bfloat16 *Ah_g, *Al_g, *Wh, *Wl; const float* bias;
    if      (mode == 0) { Ah_g = g_xh; Al_g = g_xl; Wh = g_wqh; Wl = g_wql; bias = b0; }
    else if (mode == 1) { Ah_g = g_xh; Al_g = g_xl; Wh = g_wkh; Wl = g_wkl; bias = b1; }
    else if (mode == 2) { Ah_g = g_xh; Al_g = g_xl; Wh = g_wvh; Wl = g_wvl; bias = b2; }
    else                { Ah_g = g_ah; Al_g = g_al; Wh = g_woh; Wl = g_wol; bias = b0; }

    const int tid = threadIdx.x;
    const int lane = tid & 31;
    const int wid = tid >> 5;
    const int wm = wid & 3;
    const int wn = wid >> 2;
    const int n0 = blockIdx.x * 128;
    const int m0 = blockIdx.y * 128;
    const uint32_t sb = smem_u32(smem);

    auto fill = [&](int c, int s) {
        const uint32_t stg = sb + s * STAGE_B;
#pragma unroll
        for (int i = 0; i < 2; i++) {
            const int idx = tid + i * 256;
            const int r = idx >> 2, q = idx & 3;
            const int kk = c * 32 + q * 8;
            size_t aoff;
            if (mode < 3) {
                aoff = (size_t)(m0 + r) * CD + kk;
            } else {
                const int m = m0 + r;
                aoff = (((size_t)((m >> 11) * CH + (kk >> 6))) * CT + (m & (CT - 1))) * CHD + (kk & 63);
            }
            const uint32_t da = stg + (uint32_t)(r * LDA + q * 8) * 2;
            CP16(da,          __cvta_generic_to_global(Ah_g + aoff));
            CP16(da + TILE_B, __cvta_generic_to_global(Al_g + aoff));
            const size_t boff = (size_t)(n0 + r) * CD + kk;
            CP16(da + 2 * TILE_B, __cvta_generic_to_global(Wh + boff));
            CP16(da + 3 * TILE_B, __cvta_generic_to_global(Wl + boff));
        }
    };

    const uint32_t offA = (uint32_t)((32 * wm + (lane & 15)) * LDA + (lane >> 4) * 8) * 2;
    const uint32_t offB = (uint32_t)((64 * wn + (lane & 7)) * LDA + ((lane >> 3) & 1) * 8) * 2;

    float d[2][8][4];
#pragma unroll
    for (int f = 0; f < 2; f++)
#pragma unroll
        for (int j = 0; j < 8; j++)
#pragma unroll
            for (int e = 0; e < 4; e++) d[f][j][e] = 0.f;

    fill(0, 0); CP_COMMIT();
    fill(1, 1); CP_COMMIT();

    for (int c = 0; c < 32; c++) {
        const int s = c % 3;
        if (c + 2 < 32) fill(c + 2, (c + 2) % 3);
        CP_COMMIT();
        CP_WAIT2();
        __syncthreads();

        const uint32_t stg = sb + s * STAGE_B;
#pragma unroll
        for (int kk = 0; kk < 2; kk++) {
            uint32_t ah[2][4], al[2][4], bh[8][2], bl[8][2];
            const uint32_t ka = stg + offA + kk * 32;
            const uint32_t kb = stg + offB + kk * 32;
#pragma unroll
            for (int f = 0; f < 2; f++) {
                ldsm_x4(ah[f], ka + f * (16 * LDA * 2));
                ldsm_x4(al[f], ka + f * (16 * LDA * 2) + TILE_B);
            }
#pragma unroll
            for (int j = 0; j < 8; j++) {
                ldsm_x2(bh[j], kb + j * (8 * LDA * 2) + 2 * TILE_B);
                ldsm_x2(bl[j], kb + j * (8 * LDA * 2) + 3 * TILE_B);
            }
#pragma unroll
            for (int f = 0; f < 2; f++)
#pragma unroll
                for (int j = 0; j < 8; j++) {
                    mma_bf16(d[f][j], ah[f], bh[j]);
                    mma_bf16(d[f][j], ah[f], bl[j]);
                    mma_bf16(d[f][j], al[f], bh[j]);
                }
        }
        __syncthreads();
    }

    // Epilogue. Thread holds (row, row+8) x (n, n+1) per fragment.
    const int q4 = lane >> 2;
    const int p2 = (lane & 3) * 2;
    const float qscale = (mode == 0) ? 0.125f : 1.0f;
#pragma unroll
    for (int f = 0; f < 2; f++) {
#pragma unroll
        for (int rr = 0; rr < 2; rr++) {
            const int mrow = m0 + 32 * wm + 16 * f + q4 + rr * 8;
            const int bb = mrow >> 11;
            const int tt = mrow & (CT - 1);
#pragma unroll
            for (int j = 0; j < 8; j++) {
                const int n = n0 + 64 * wn + 8 * j + p2;
                const float2 bv = *(const float2*)(bias + n);
                float v0 = d[f][j][rr * 2 + 0] + bv.x;
                float v1 = d[f][j][rr * 2 + 1] + bv.y;
                if (mode == 3) {
                    *(float2*)(outO + (size_t)mrow * CD + n) = make_float2(v0, v1);
                } else if (mode < 2) {
                    // Q/K: RoPE, scale (Q), split hi/lo, store [B,H,T,HD]
                    const int h = n >> 6, hd = n & 63;
                    const int p = hd >> 1;
                    const float cc = cosb[tt * (CHD / 2) + p];
                    const float ss = sinb[tt * (CHD / 2) + p];
                    const float o0 = (v0 * cc - v1 * ss) * qscale;
                    const float o1 = (v0 * ss + v1 * cc) * qscale;
                    const __nv_bfloat16 h0 = __float2bfloat16(o0);
                    const __nv_bfloat16 h1 = __float2bfloat16(o1);
                    const size_t base = (((size_t)(bb * CH + h)) * CT + tt) * CHD + hd;
                    __nv_bfloat16* oh = (mode == 0) ? g_qh : g_kh;
                    __nv_bfloat16* ol = (mode == 0) ? g_ql : g_kl;
                    *(uint32_t*)(oh + base) = packbf2(o0, o1);  // rn-packed hi
                    *(uint32_t*)(ol + base) = packbf2(o0 - __bfloat162float(h0),
                                                      o1 - __bfloat162float(h1));
                } else {
                    // V: split hi/lo, store TRANSPOSED [B,H,HD,T]
                    const int h = n >> 6, hd = n & 63;
                    const int bh = bb * CH + h;
                    const __nv_bfloat16 h0 = __float2bfloat16(v0);
                    const __nv_bfloat16 h1 = __float2bfloat16(v1);
                    const size_t b0i = ((size_t)(bh * CHD + hd)) * CT + tt;
                    const size_t b1i = ((size_t)(bh * CHD + hd + 1)) * CT + tt;
                    g_vth[b0i] = h0;
                    g_vth[b1i] = h1;
                    g_vtl[b0i] = __float2bfloat16(v0 - __bfloat162float(h0));
                    g_vtl[b1i] = __float2bfloat16(v1 - __bfloat162float(h1));
                }
            }
        }
    }
}

// ---------------------------------------------------------------------------
// Kernel 2: causal flash attention on HMMA (mma.sync bf16 + hi/lo emulation).
// BM=BN=64, 4 warps (m16 each), K/Vt double-buffered cp.async.
// smem: Qh|Ql (18432) + 2 stages of [Kh|Kl|Vth|Vtl] (36864 each) = 92160 B.
// ---------------------------------------------------------------------------
#define AT_LDA  72
#define AT_ROWB (AT_LDA * 2)          // 144 B per row
#define AT_TILEB (64 * AT_ROWB)       // 9216 B per 64x64 bf16 tile
#define AT_QOFF 0
#define AT_STG0 (2 * AT_TILEB)        // 18432
#define AT_STAGEB (4 * AT_TILEB)      // 36864
#define ATT_SMEM (AT_STG0 + 2 * AT_STAGEB)  // 92160

__global__ __launch_bounds__(128) void attn_hmma_kernel()
{
    extern __shared__ __align__(16) char smem[];
    const uint32_t sb = smem_u32(smem);
    const int tid = threadIdx.x;
    const int lane = tid & 31;
    const int w = tid >> 5;                  // warp 0..3, rows 16w..16w+15
    const int bh = blockIdx.y;
    const int qt = (gridDim.x - 1) - blockIdx.x;   // heavy tiles first
    const int q0 = qt * 64;

    // Q tile cp.async (hi + lo): 64 rows x 8 x16B chunks each
    {
        const __nv_bfloat16* qh = g_qh + ((size_t)bh * CT + q0) * CHD;
        const __nv_bfloat16* ql = g_ql + ((size_t)bh * CT + q0) * CHD;
#pragma unroll
        for (int i = 0; i < 4; i++) {
            const int idx = tid + i * 128;       // 0..511
            const int r = idx >> 3, cc = idx & 7;
            const uint32_t dst = sb + AT_QOFF + (uint32_t)(r * AT_ROWB + cc * 16);
            const size_t off = (size_t)r * CHD + cc * 8;
            CP16(dst,            __cvta_generic_to_global(qh + off));
            CP16(dst + AT_TILEB, __cvta_generic_to_global(ql + off));
        }
    }

    auto fill = [&](int kt, int s) {
        const uint32_t stg = sb + AT_STG0 + s * AT_STAGEB;
        const int k0 = kt * 64;
        const __nv_bfloat16* kh = g_kh + ((size_t)bh * CT + k0) * CHD;
        const __nv_bfloat16* kl = g_kl + ((size_t)bh * CT + k0) * CHD;
#pragma unroll
        for (int i = 0; i < 4; i++) {
            const int idx = tid + i * 128;
            const int r = idx >> 3, cc = idx & 7;
            const uint32_t dk = stg + (uint32_t)(r * AT_ROWB + cc * 16);
            const size_t koff = (size_t)r * CHD + cc * 8;
            CP16(dk,            __cvta_generic_to_global(kh + koff));
            CP16(dk + AT_TILEB, __cvta_generic_to_global(kl + koff));
            // Vt rows: r = hd, cols = keys
            const uint32_t dv = stg + 2 * AT_TILEB + (uint32_t)(r * AT_ROWB + cc * 16);
            const size_t voff = ((size_t)(bh * CHD + r)) * CT + k0 + cc * 8;
            CP16(dv,            __cvta_generic_to_global(g_vth + voff));
            CP16(dv + AT_TILEB, __cvta_generic_to_global(g_vtl + voff));
        }
    };

    fill(0, 0); CP_COMMIT();

    float s[8][4], o[8][4];
#pragma unroll
    for (int j = 0; j < 8; j++)
#pragma unroll
        for (int e = 0; e < 4; e++) o[j][e] = 0.f;
    float m_old[2] = {-1e30f, -1e30f}, lsum[2] = {0.f, 0.f};

    const uint32_t qbase = sb + AT_QOFF + (uint32_t)(((16 * w + (lane & 15)) * AT_LDA + (lane >> 4) * 8) * 2);
    const uint32_t brow  = (uint32_t)((((lane & 7)) * AT_LDA + ((lane >> 3) & 1) * 8) * 2);
    const int rbase = 16 * w + (lane >> 2);

    for (int kt = 0; kt <= qt; kt++) {
        if (kt < qt) { fill(kt + 1, (kt + 1) & 1); CP_COMMIT(); CP_WAIT1(); }
        else         { CP_WAIT0(); }
        __syncthreads();
        const uint32_t stg = sb + AT_STG0 + (kt & 1) * AT_STAGEB;

        // ---- S = Q K^T (3 passes) ----
#pragma unroll
        for (int j = 0; j < 8; j++)
#pragma unroll
            for (int e = 0; e < 4; e++) s[j][e] = 0.f;
#pragma unroll
        for (int kk = 0; kk < 4; kk++) {
            uint32_t qh[4], ql[4];
            ldsm_x4(qh, qbase + kk * 32);
            ldsm_x4(ql, qbase + kk * 32 + AT_TILEB);
#pragma unroll
            for (int j = 0; j < 8; j++) {
                uint32_t kh2[2], kl2[2];
                const uint32_t ka = stg + j * (8 * AT_ROWB) + brow + kk * 32;
                ldsm_x2(kh2, ka);
                ldsm_x2(kl2, ka + AT_TILEB);
                mma_bf16(s[j], qh, kh2);
                mma_bf16(s[j], qh, kl2);
                mma_bf16(s[j], ql, kh2);
            }
        }

        // ---- causal mask on diagonal tile ----
        if (kt == qt) {
#pragma unroll
            for (int j = 0; j < 8; j++)
#pragma unroll
                for (int e = 0; e < 2; e++)
#pragma unroll
                    for (int c = 0; c < 2; c++) {
                        const int col = 8 * j + (lane & 3) * 2 + c;
                        const int row = rbase + 8 * e;
                        if (col > row) s[j][2 * e + c] = -1e30f;
                    }
        }

        // ---- online softmax (rows rbase, rbase+8) ----
#pragma unroll
        for (int e = 0; e < 2; e++) {
            float mx = -1e30f;
#pragma unroll
            for (int j = 0; j < 8; j++)
                mx = fmaxf(mx, fmaxf(s[j][2 * e], s[j][2 * e + 1]));
            mx = fmaxf(mx, __shfl_xor_sync(0xffffffffu, mx, 1));
            mx = fmaxf(mx, __shfl_xor_sync(0xffffffffu, mx, 2));
            const float mn = fmaxf(m_old[e], mx);
            float sum = 0.f;
#pragma unroll
            for (int j = 0; j < 8; j++) {
                const float p0 = __expf(s[j][2 * e]     - mn);
                const float p1 = __expf(s[j][2 * e + 1] - mn);
                s[j][2 * e] = p0; s[j][2 * e + 1] = p1;
                sum += p0 + p1;
            }
            sum += __shfl_xor_sync(0xffffffffu, sum, 1);
            sum += __shfl_xor_sync(0xffffffffu, sum, 2);
            const float scl = __expf(m_old[e] - mn);
            lsum[e] = lsum[e] * scl + sum;
            m_old[e] = mn;
#pragma unroll
            for (int j = 0; j < 8; j++) {
                o[j][2 * e]     *= scl;
                o[j][2 * e + 1] *= scl;
            }
        }

        // ---- O += P V (3 passes); P frags straight from S regs ----
        const uint32_t vbase = stg + 2 * AT_TILEB;
#pragma unroll
        for (int kk = 0; kk < 4; kk++) {
            const int t0 = 2 * kk, t1 = 2 * kk + 1;
            uint32_t aH[4], aL[4];
            {
                const float p00 = s[t0][0], p01 = s[t0][1], p10 = s[t0][2], p11 = s[t0][3];
                const float q00 = s[t1][0], q01 = s[t1][1], q10 = s[t1][2], q11 = s[t1][3];
                const float h00 = __bfloat162float(__float2bfloat16(p00));
                const float h01 = __bfloat162float(__float2bfloat16(p01));
                const float h10 = __bfloat162float(__float2bfloat16(p10));
                const float h11 = __bfloat162float(__float2bfloat16(p11));
                const float g00 = __bfloat162float(__float2bfloat16(q00));
                const float g01 = __bfloat162float(__float2bfloat16(q01));
                const float g10 = __bfloat162float(__float2bfloat16(q10));
                const float g11 = __bfloat162float(__float2bfloat16(q11));
                aH[0] = packbf2(h00, h01); aH[1] = packbf2(h10, h11);
                aH[2] = packbf2(g00, g01); aH[3] = packbf2(g10, g11);
                aL[0] = packbf2(p00 - h00, p01 - h01); aL[1] = packbf2(p10 - h10, p11 - h11);
                aL[2] = packbf2(q00 - g00, q01 - g01); aL[3] = packbf2(q10 - g10, q11 - g11);
            }
#pragma unroll
            for (int j = 0; j < 8; j++) {
                uint32_t vh2[2], vl2[2];
                const uint32_t va = vbase + j * (8 * AT_ROWB) + brow + kk * 32;
                ldsm_x2(vh2, va);
                ldsm_x2(vl2, va + AT_TILEB);
                mma_bf16(o[j], aH, vh2);
                mma_bf16(o[j], aH, vl2);
                mma_bf16(o[j], aL, vh2);
            }
        }
        __syncthreads();   // stage reuse guard
    }

    // ---- epilogue: normalize, split hi/lo, store [B,H,T,HD] ----
#pragma unroll
    for (int e = 0; e < 2; e++) {
        const float inv = 1.0f / lsum[e];
        const int t = q0 + rbase + 8 * e;
        const size_t base = ((size_t)bh * CT + t) * CHD;
#pragma unroll
        for (int j = 0; j < 8; j++) {
            const int hd = 8 * j + (lane & 3) * 2;
            const float v0 = o[j][2 * e] * inv;
            const float v1 = o[j][2 * e + 1] * inv;
            const float h0 = __bfloat162float(__float2bfloat16(v0));
            const float h1 = __bfloat162float(__float2bfloat16(v1));
            *(uint32_t*)(g_ah + base + hd) = packbf2(v0, v1);
            *(uint32_t*)(g_al + base + hd) = packbf2(v0 - h0, v1 - h1);
        }
    }
}

// ---------------------------------------------------------------------------
extern "C" void kernel_launch(void* const* d_in, const int* in_sizes, int n_in,
                              void* d_out, int out_size)
{
    const float* x    = (const float*)d_in[0];
    const float* cosb = (const float*)d_in[1];
    const float* sinb = (const float*)d_in[2];
    const float* Wq   = (const float*)d_in[3];
    const float* bq   = (const float*)d_in[4];
    const float* Wk   = (const float*)d_in[5];
    const float* bk   = (const float*)d_in[6];
    const float* Wv   = (const float*)d_in[7];
    const float* bv   = (const float*)d_in[8];
    const float* Wo   = (const float*)d_in[9];
    const float* bo   = (const float*)d_in[10];
    float* out = (float*)d_out;

    cudaFuncSetAttribute(gemm_hmma_kernel, cudaFuncAttributeMaxDynamicSharedMemorySize, GEMM_SMEM);
    cudaFuncSetAttribute(attn_hmma_kernel, cudaFuncAttributeMaxDynamicSharedMemorySize, ATT_SMEM);

    // 1) fp32 -> bf16 hi/lo conversions
    convert_kernel<<<dim3(512, 1, 5), 256>>>(x, Wq, Wk, Wv, Wo);

    // 2) QKV projections + bias + RoPE (HMMA) -> bf16 hi/lo (V transposed)
    gemm_hmma_kernel<<<dim3(CD / 128, MROWS / 128, 3), 256, GEMM_SMEM>>>(
        bq, bk, bv, cosb, sinb, nullptr, 0);

    // 3) causal flash attention (HMMA) -> bf16 hi/lo attention output
    attn_hmma_kernel<<<dim3(CT / 64, CB * CH), 128, ATT_SMEM>>>();

    // 4) output projection (HMMA) -> d_out
    gemm_hmma_kernel<<<dim3(CD / 128, MROWS / 128, 1), 256, GEMM_SMEM>>>(
        bo, bo, bo, cosb, sinb, out, 3);
}